// round 7
// baseline (speedup 1.0000x reference)
#include <cuda_runtime.h>
#include <cuda_bf16.h>
#include <cuda_fp16.h>
#include <math.h>

// Fixed problem shape
#define BB   4
#define NN   32768
#define KK   16
#define CIN  32
#define HH   32
#define COUT 32
#define PP   3

#define GTOT (BB * NN)          // 131072 nodes
#define ETOT (BB * NN * KK)     // 2097152 edges
#define MELEMS (GTOT * HH)      // 4194304 elements
#define NBLK 512                // scan blocks: 512 * 256 = GTOT

// Scratch (__device__ globals; no allocation allowed)
__device__ __half  g_mh[MELEMS];      // m[node,h] fp16 (8 MB)
__device__ float   g_acc[MELEMS];     // per-node accumulated hidden (16 MB)
__device__ float4  g_grid4[GTOT];     // packed grid coords
__device__ int     g_cnt[GTOT];       // in-degree histogram
__device__ int     g_start[GTOT + 1]; // segment starts (exclusive scan)
__device__ int     g_cursor[GTOT];    // scatter cursors
__device__ int     g_bsum[NBLK];      // per-block sums for scan
__device__ int     g_sorted[ETOT];    // src node id, grouped by dst (8 MB)

// Small weights in constant memory
__constant__ float cW1[HH * CIN];
__constant__ float cb1[HH];
__constant__ float cbw[HH];
__constant__ float cW2[COUT * HH];
__constant__ float cb2[COUT];

// ---------------------------------------------------------------------------
// gemm1 fused, 2 nodes per thread. (round-5/6 version, minus acc zeroing —
// the gather pass now writes every acc row unconditionally)
// ---------------------------------------------------------------------------
__global__ void gemm1_kernel(const float* __restrict__ x,
                             const float* __restrict__ gw,
                             const float* __restrict__ grid) {
    int i  = blockIdx.x * blockDim.x + threadIdx.x;  // [0, GTOT/2)
    int g0 = i;
    int g1 = i + GTOT / 2;

    const float* xb0 = x + (size_t)(g0 >> 15) * CIN * NN + (g0 & (NN - 1));
    const float* xb1 = x + (size_t)(g1 >> 15) * CIN * NN + (g1 & (NN - 1));

    float a0[HH], a1[HH];
#pragma unroll
    for (int h = 0; h < HH; h++) { a0[h] = 0.f; a1[h] = 0.f; }

#pragma unroll
    for (int c = 0; c < CIN; c++) {
        float xv0 = xb0[(size_t)c * NN];
        float xv1 = xb1[(size_t)c * NN];
#pragma unroll
        for (int h = 0; h < HH; h++) {
            float w = cW1[h * CIN + c];
            a0[h] += w * xv0;
            a1[h] += w * xv1;
        }
    }

    float w0 = gw[g0];
    float w1 = gw[g1];

#pragma unroll
    for (int node = 0; node < 2; node++) {
        int g = node ? g1 : g0;
        float wgt = node ? w1 : w0;
        const float* a = node ? a1 : a0;

        uint4 ov[4];                                 // 32 halves = 64 B
        unsigned int* oh = reinterpret_cast<unsigned int*>(ov);
#pragma unroll
        for (int hp = 0; hp < HH / 2; hp++) {
            int h0 = 2 * hp, h1 = 2 * hp + 1;
            float r0 = cbw[h0] * 0.3183098861837907f;
            float r1 = cbw[h1] * 0.3183098861837907f;
            float m0 = (a[h0] + cb1[h0]) * wgt * sqrtf(r0 * r0 * r0);
            float m1 = (a[h1] + cb1[h1]) * wgt * sqrtf(r1 * r1 * r1);
            __half2 h2 = __floats2half2_rn(m0, m1);
            oh[hp] = *reinterpret_cast<unsigned int*>(&h2);
        }
        uint4* mo = reinterpret_cast<uint4*>(g_mh + (size_t)g * HH);
#pragma unroll
        for (int q = 0; q < 4; q++) mo[q] = ov[q];

        const float* gp = grid + (size_t)g * PP;
        g_grid4[g] = make_float4(gp[0], gp[1], gp[2], 0.f);
    }
}

// ---------------------------------------------------------------------------
// Counting sort by dst
// ---------------------------------------------------------------------------
__global__ void zero_cnt_kernel() {
    int i = blockIdx.x * blockDim.x + threadIdx.x;   // GTOT/4 threads
    reinterpret_cast<int4*>(g_cnt)[i] = make_int4(0, 0, 0, 0);
}

__global__ void hist_kernel(const int* __restrict__ ed) {
    int e = blockIdx.x * blockDim.x + threadIdx.x;   // ETOT threads
    int b = e >> 19;
    int d = __ldg(ed + e) + (b << 15);
    atomicAdd(&g_cnt[d], 1);
}

// S1: per-block (256-wide) sums of g_cnt -> g_bsum
__global__ void scan1_kernel() {
    __shared__ int buf[256];
    int t = threadIdx.x;
    buf[t] = g_cnt[blockIdx.x * 256 + t];
    __syncthreads();
    for (int o = 128; o > 0; o >>= 1) {
        if (t < o) buf[t] += buf[t + o];
        __syncthreads();
    }
    if (t == 0) g_bsum[blockIdx.x] = buf[0];
}

// S2: exclusive scan of g_bsum (NBLK=512 elements, one block of 512)
__global__ void scan2_kernel() {
    __shared__ int buf[NBLK];
    int t = threadIdx.x;
    int orig = g_bsum[t];
    buf[t] = orig;
    __syncthreads();
    for (int o = 1; o < NBLK; o <<= 1) {
        int v = (t >= o) ? buf[t - o] : 0;
        __syncthreads();
        buf[t] += v;
        __syncthreads();
    }
    g_bsum[t] = buf[t] - orig;                        // exclusive
    if (t == 0) g_start[GTOT] = ETOT;                 // sentinel
}

// S3: within-block exclusive scan + block offset -> g_start, g_cursor
__global__ void scan3_kernel() {
    __shared__ int buf[256];
    int t = threadIdx.x;
    int i = blockIdx.x * 256 + t;
    int orig = g_cnt[i];
    buf[t] = orig;
    __syncthreads();
    for (int o = 1; o < 256; o <<= 1) {
        int v = (t >= o) ? buf[t - o] : 0;
        __syncthreads();
        buf[t] += v;
        __syncthreads();
    }
    int start = g_bsum[blockIdx.x] + buf[t] - orig;
    g_start[i]  = start;
    g_cursor[i] = start;
}

// Scatter: sorted[pos] = src (global node id), grouped by dst
__global__ void scatter_kernel(const int* __restrict__ es,
                               const int* __restrict__ ed) {
    int e = blockIdx.x * blockDim.x + threadIdx.x;   // ETOT threads
    int b   = e >> 19;
    int off = b << 15;
    int s = __ldg(es + e) + off;
    int d = __ldg(ed + e) + off;
    int pos = atomicAdd(&g_cursor[d], 1);
    g_sorted[pos] = s;
}

// ---------------------------------------------------------------------------
// Gather: warp per dst node, lane = hidden channel.
// acc[g,h] = sum over segment:  m_h[src,h] * exp(-bw[h]*|grid[src]-grid[g]|^2)
// No atomics; one coalesced 128B store per node.
// ---------------------------------------------------------------------------
__global__ void gather_kernel() {
    int warp = (blockIdx.x * blockDim.x + threadIdx.x) >> 5;  // node id
    int lane = threadIdx.x & 31;

    int beg = g_start[warp];
    int end = g_start[warp + 1];

    float4 gd = g_grid4[warp];                       // broadcast
    float nb = cbw[lane] * (-1.4426950408889634f);   // -bw*log2e

    float acc = 0.f;
    for (int e = beg; e < end; e++) {
        int s = __ldg(g_sorted + e);                 // broadcast, L1-resident
        float4 gs = g_grid4[s];                      // broadcast gather
        float dx = gs.x - gd.x;
        float dy = gs.y - gd.y;
        float dz = gs.z - gd.z;
        float d2 = dx * dx + dy * dy + dz * dz;
        float mv = __half2float(g_mh[s * HH + lane]); // 64B coalesced
        float ex;
        asm("ex2.approx.f32 %0, %1;" : "=f"(ex) : "f"(nb * d2));
        acc += mv * ex;
    }
    g_acc[(size_t)warp * HH + lane] = acc;           // coalesced store
}

// ---------------------------------------------------------------------------
// gemm2: out[b,o,n] = sum_h W2[o,h]*acc[g,h] + b2[o]   [unchanged]
// ---------------------------------------------------------------------------
__global__ void gemm2_kernel(float* __restrict__ out) {
    int g = blockIdx.x * blockDim.x + threadIdx.x;
    int b = g >> 15;
    int n = g & (NN - 1);

    float a[HH];
    const float4* av = reinterpret_cast<const float4*>(g_acc + (size_t)g * HH);
#pragma unroll
    for (int i = 0; i < HH / 4; i++) {
        float4 v = av[i];
        a[4 * i + 0] = v.x;
        a[4 * i + 1] = v.y;
        a[4 * i + 2] = v.z;
        a[4 * i + 3] = v.w;
    }

    float* ob = out + (size_t)b * COUT * NN + n;
#pragma unroll
    for (int o = 0; o < COUT; o++) {
        float s = cb2[o];
#pragma unroll
        for (int h = 0; h < HH; h++)
            s += cW2[o * HH + h] * a[h];
        ob[(size_t)o * NN] = s;
    }
}

// ---------------------------------------------------------------------------
// Launcher
// inputs: 0:x 1:grid 2:grid_weight 3:edge_src 4:edge_dst 5:W1 6:b1 7:W2 8:b2 9:baseweight
// ---------------------------------------------------------------------------
extern "C" void kernel_launch(void* const* d_in, const int* in_sizes, int n_in,
                              void* d_out, int out_size) {
    const float* x    = (const float*)d_in[0];
    const float* grid = (const float*)d_in[1];
    const float* gw   = (const float*)d_in[2];
    const int*   es   = (const int*)d_in[3];
    const int*   ed   = (const int*)d_in[4];
    const float* W1   = (const float*)d_in[5];
    const float* b1   = (const float*)d_in[6];
    const float* W2   = (const float*)d_in[7];
    const float* b2   = (const float*)d_in[8];
    const float* bw   = (const float*)d_in[9];
    float* out = (float*)d_out;

    cudaMemcpyToSymbolAsync(cW1, W1, HH * CIN * sizeof(float), 0,
                            cudaMemcpyDeviceToDevice, 0);
    cudaMemcpyToSymbolAsync(cb1, b1, HH * sizeof(float), 0,
                            cudaMemcpyDeviceToDevice, 0);
    cudaMemcpyToSymbolAsync(cbw, bw, HH * sizeof(float), 0,
                            cudaMemcpyDeviceToDevice, 0);
    cudaMemcpyToSymbolAsync(cW2, W2, COUT * HH * sizeof(float), 0,
                            cudaMemcpyDeviceToDevice, 0);
    cudaMemcpyToSymbolAsync(cb2, b2, COUT * sizeof(float), 0,
                            cudaMemcpyDeviceToDevice, 0);

    // fc1 + gauss-norm + grid pack (independent of sort chain)
    gemm1_kernel<<<(GTOT / 2) / 256, 256>>>(x, gw, grid);

    // counting sort by dst
    zero_cnt_kernel<<<(GTOT / 4) / 256, 256>>>();
    hist_kernel<<<ETOT / 256, 256>>>(ed);
    scan1_kernel<<<NBLK, 256>>>();
    scan2_kernel<<<1, NBLK>>>();
    scan3_kernel<<<NBLK, 256>>>();
    scatter_kernel<<<ETOT / 256, 256>>>(es, ed);

    // gather: warp per node, no atomics
    gather_kernel<<<(GTOT * 32) / 256, 256>>>();

    // fc2 + transpose
    gemm2_kernel<<<GTOT / 256, 256>>>(out);
}

// round 8
// speedup vs baseline: 1.7806x; 1.7806x over previous
#include <cuda_runtime.h>
#include <cuda_bf16.h>
#include <cuda_fp16.h>
#include <math.h>

// Fixed problem shape
#define BB   4
#define NN   32768
#define KK   16
#define CIN  32
#define HH   32
#define COUT 32
#define PP   3

#define GTOT (BB * NN)          // 131072 nodes
#define ETOT (BB * NN * KK)     // 2097152 edges
#define MELEMS (GTOT * HH)      // 4194304 elements

// Scratch (__device__ globals; no allocation allowed)
__device__ __half  g_mh[MELEMS];   // m[node,h] fp16 (8 MB)
__device__ float   g_acc[MELEMS];  // segment-sum accumulator (16 MB)
__device__ float4  g_grid4[GTOT];  // packed grid coords

// Packed weights (pack_kernel fills g_pack; one D2D memcpy -> c_pack)
struct Pack {
    float2 w1t[CIN * (HH / 2)];    // [c][hp] = {W1[2hp,c], W1[2hp+1,c]}
    float2 w2t[HH * (COUT / 2)];   // [h][op] = {W2[2op,h], W2[2op+1,h]}
    float  b1[HH];
    float  sc[HH];                 // sqrt((bw/pi)^3)
    float  nb[HH];                 // -bw * log2(e)
    float  b2[COUT];
};
__device__  Pack g_pack;
__constant__ Pack c_pack;

// ---- f32x2 helpers ----
__device__ __forceinline__ unsigned long long pk2(float lo, float hi) {
    unsigned long long r;
    asm("mov.b64 %0, {%1,%2};" : "=l"(r) : "f"(lo), "f"(hi));
    return r;
}
__device__ __forceinline__ float2 upk2(unsigned long long v) {
    float2 r;
    asm("mov.b64 {%0,%1}, %2;" : "=f"(r.x), "=f"(r.y) : "l"(v));
    return r;
}
__device__ __forceinline__ void ffma2(unsigned long long& acc,
                                      unsigned long long a,
                                      unsigned long long b) {
    asm("fma.rn.f32x2 %0, %1, %2, %0;" : "+l"(acc) : "l"(a), "l"(b));
}

// ---------------------------------------------------------------------------
// Prep: pack W1/W2 pairs + fold bw transforms. One block.
// ---------------------------------------------------------------------------
__global__ void pack_kernel(const float* __restrict__ W1,
                            const float* __restrict__ b1,
                            const float* __restrict__ W2,
                            const float* __restrict__ b2,
                            const float* __restrict__ bw) {
    int t = threadIdx.x;
    for (int i = t; i < CIN * (HH / 2); i += blockDim.x) {
        int c  = i / (HH / 2);
        int hp = i % (HH / 2);
        g_pack.w1t[i] = make_float2(W1[(2 * hp) * CIN + c],
                                    W1[(2 * hp + 1) * CIN + c]);
    }
    for (int i = t; i < HH * (COUT / 2); i += blockDim.x) {
        int h  = i / (COUT / 2);
        int op = i % (COUT / 2);
        g_pack.w2t[i] = make_float2(W2[(2 * op) * HH + h],
                                    W2[(2 * op + 1) * HH + h]);
    }
    if (t < HH) {
        g_pack.b1[t] = b1[t];
        float w = bw[t];
        float r = w * 0.3183098861837907f;          // bw/pi
        g_pack.sc[t] = sqrtf(r * r * r);
        g_pack.nb[t] = -w * 1.4426950408889634f;    // -bw*log2e
        g_pack.b2[t] = b2[t];
    }
}

// ---------------------------------------------------------------------------
// gemm1 fused (1 node/thread, f32x2):
//   m_h[g,h] = half((W1x+b1)*gw*sc[h]) ; acc[g,:]=0 ; grid4 pack.
// ---------------------------------------------------------------------------
__global__ void gemm1_kernel(const float* __restrict__ x,
                             const float* __restrict__ gw,
                             const float* __restrict__ grid) {
    int g = blockIdx.x * blockDim.x + threadIdx.x;   // node id
    int b = g >> 15;                                 // NN = 2^15
    int n = g & (NN - 1);
    const float* xb = x + (size_t)b * CIN * NN + n;

    const unsigned long long* w1u =
        reinterpret_cast<const unsigned long long*>(c_pack.w1t);

    unsigned long long acc2[HH / 2];
#pragma unroll
    for (int hp = 0; hp < HH / 2; hp++) acc2[hp] = 0ull;

#pragma unroll
    for (int c = 0; c < CIN; c++) {
        float xv = xb[(size_t)c * NN];               // coalesced
        unsigned long long xx = pk2(xv, xv);
#pragma unroll
        for (int hp = 0; hp < HH / 2; hp++)
            ffma2(acc2[hp], w1u[c * (HH / 2) + hp], xx);
    }

    float w = gw[g];
    uint4 ov[4];                                     // 32 halves = 64 B
    unsigned int* oh = reinterpret_cast<unsigned int*>(ov);
#pragma unroll
    for (int hp = 0; hp < HH / 2; hp++) {
        float2 a = upk2(acc2[hp]);
        float m0 = (a.x + c_pack.b1[2 * hp])     * w * c_pack.sc[2 * hp];
        float m1 = (a.y + c_pack.b1[2 * hp + 1]) * w * c_pack.sc[2 * hp + 1];
        __half2 h2 = __floats2half2_rn(m0, m1);
        oh[hp] = *reinterpret_cast<unsigned int*>(&h2);
    }
    uint4* mo = reinterpret_cast<uint4*>(g_mh + (size_t)g * HH);
#pragma unroll
    for (int q = 0; q < 4; q++) mo[q] = ov[q];

    float4* ao = reinterpret_cast<float4*>(g_acc + (size_t)g * HH);
#pragma unroll
    for (int j = 0; j < HH / 4; j++) ao[j] = make_float4(0.f, 0.f, 0.f, 0.f);

    const float* gp = grid + (size_t)g * PP;
    g_grid4[g] = make_float4(gp[0], gp[1], gp[2], 0.f);
}

// ---------------------------------------------------------------------------
// Edge kernel: byte-identical structure to round 6 (65us, known floor).
// Warp owns 32 edges; phase 2 retires 4 edges/iter via red.global.add.v4.f32.
// ---------------------------------------------------------------------------
__global__ void edge_kernel(const int* __restrict__ es,
                            const int* __restrict__ ed) {
    __shared__ float4 stage[8][32];                  // 8 warps/block
    int tid  = blockIdx.x * blockDim.x + threadIdx.x;
    int lane = threadIdx.x & 31;
    int w    = threadIdx.x >> 5;

    // ---- phase 1: lane = edge ----
    int e   = tid;
    int b   = e >> 19;                               // NN*KK = 2^19
    int off = b << 15;                               // b * NN
    int s   = __ldg(es + e) + off;
    int d   = __ldg(ed + e) + off;

    float4 gs = g_grid4[s];
    float4 gd = g_grid4[d];
    float dx = gs.x - gd.x;
    float dy = gs.y - gd.y;
    float dz = gs.z - gd.z;
    float d2 = dx * dx + dy * dy + dz * dz;

    stage[w][lane] = make_float4(__int_as_float(s * HH),
                                 __int_as_float(d * HH), d2, 0.f);
    __syncwarp();

    // ---- phase 2: grp = edge of quad, c0 = first of 4 channels ----
    int grp = lane >> 3;                             // 0..3
    int c0  = (lane & 7) * 4;                        // 0,4,...,28

    float nb0 = c_pack.nb[c0];
    float nb1 = c_pack.nb[c0 + 1];
    float nb2 = c_pack.nb[c0 + 2];
    float nb3 = c_pack.nb[c0 + 3];

#pragma unroll
    for (int i = 0; i < 32; i += 4) {
        float4 p  = stage[w][i + grp];               // 4-way LDS.128 broadcast
        int   si  = __float_as_int(p.x);
        int   di  = __float_as_int(p.y);
        float d2i = p.z;

        unsigned long long mraw =
            *reinterpret_cast<const unsigned long long*>(g_mh + si + c0);
        __half2 hA = *reinterpret_cast<__half2*>(&mraw);
        __half2 hB = *(reinterpret_cast<__half2*>(&mraw) + 1);
        float2 fA = __half22float2(hA);
        float2 fB = __half22float2(hB);

        float e0, e1, e2, e3;
        asm("ex2.approx.f32 %0, %1;" : "=f"(e0) : "f"(nb0 * d2i));
        asm("ex2.approx.f32 %0, %1;" : "=f"(e1) : "f"(nb1 * d2i));
        asm("ex2.approx.f32 %0, %1;" : "=f"(e2) : "f"(nb2 * d2i));
        asm("ex2.approx.f32 %0, %1;" : "=f"(e3) : "f"(nb3 * d2i));

        float v0 = fA.x * e0;
        float v1 = fA.y * e1;
        float v2 = fB.x * e2;
        float v3 = fB.y * e3;

        asm volatile("red.global.add.v4.f32 [%0], {%1, %2, %3, %4};"
                     :: "l"(g_acc + di + c0),
                        "f"(v0), "f"(v1), "f"(v2), "f"(v3)
                     : "memory");
    }
}

// ---------------------------------------------------------------------------
// gemm2 (f32x2 over output pairs): out[b,o,n] = sum_h W2[o,h]*acc[g,h] + b2[o]
// ---------------------------------------------------------------------------
__global__ void gemm2_kernel(float* __restrict__ out) {
    int g = blockIdx.x * blockDim.x + threadIdx.x;
    int b = g >> 15;
    int n = g & (NN - 1);

    float a[HH];
    const float4* av = reinterpret_cast<const float4*>(g_acc + (size_t)g * HH);
#pragma unroll
    for (int i = 0; i < HH / 4; i++) {
        float4 v = av[i];
        a[4 * i + 0] = v.x;
        a[4 * i + 1] = v.y;
        a[4 * i + 2] = v.z;
        a[4 * i + 3] = v.w;
    }

    const unsigned long long* w2u =
        reinterpret_cast<const unsigned long long*>(c_pack.w2t);

    unsigned long long s2[COUT / 2];
#pragma unroll
    for (int op = 0; op < COUT / 2; op++)
        s2[op] = pk2(c_pack.b2[2 * op], c_pack.b2[2 * op + 1]);

#pragma unroll
    for (int h = 0; h < HH; h++) {
        unsigned long long aa = pk2(a[h], a[h]);
#pragma unroll
        for (int op = 0; op < COUT / 2; op++)
            ffma2(s2[op], w2u[h * (COUT / 2) + op], aa);
    }

    float* ob = out + (size_t)b * COUT * NN + n;
#pragma unroll
    for (int op = 0; op < COUT / 2; op++) {
        float2 v = upk2(s2[op]);
        ob[(size_t)(2 * op) * NN]     = v.x;
        ob[(size_t)(2 * op + 1) * NN] = v.y;
    }
}

// ---------------------------------------------------------------------------
// Launcher
// inputs: 0:x 1:grid 2:grid_weight 3:edge_src 4:edge_dst 5:W1 6:b1 7:W2 8:b2 9:baseweight
// ---------------------------------------------------------------------------
extern "C" void kernel_launch(void* const* d_in, const int* in_sizes, int n_in,
                              void* d_out, int out_size) {
    const float* x    = (const float*)d_in[0];
    const float* grid = (const float*)d_in[1];
    const float* gw   = (const float*)d_in[2];
    const int*   es   = (const int*)d_in[3];
    const int*   ed   = (const int*)d_in[4];
    const float* W1   = (const float*)d_in[5];
    const float* b1   = (const float*)d_in[6];
    const float* W2   = (const float*)d_in[7];
    const float* b2   = (const float*)d_in[8];
    const float* bw   = (const float*)d_in[9];
    float* out = (float*)d_out;

    // 0) pack weights on device, stage into constant bank (single D2D copy)
    pack_kernel<<<1, 256>>>(W1, b1, W2, b2, bw);
    void* packAddr = nullptr;
    cudaGetSymbolAddress(&packAddr, g_pack);
    cudaMemcpyToSymbolAsync(c_pack, packAddr, sizeof(Pack), 0,
                            cudaMemcpyDeviceToDevice, 0);

    // 1) fused fc1 (f32x2) + gauss-norm + grid_weight ; zero acc ; pack grid
    gemm1_kernel<<<GTOT / 256, 256>>>(x, gw, grid);

    // 2) edge scatter: 32 edges per warp, two-phase, RED.v4
    edge_kernel<<<ETOT / 256, 256>>>(es, ed);

    // 3) fc2 (f32x2) + transpose to (B, COUT, N)
    gemm2_kernel<<<GTOT / 256, 256>>>(out);
}

// round 9
// speedup vs baseline: 1.8114x; 1.0173x over previous
#include <cuda_runtime.h>
#include <cuda_bf16.h>
#include <cuda_fp16.h>
#include <math.h>

// Fixed problem shape
#define BB   4
#define NN   32768
#define KK   16
#define CIN  32
#define HH   32
#define COUT 32
#define PP   3

#define GTOT (BB * NN)          // 131072 nodes
#define ETOT (BB * NN * KK)     // 2097152 edges
#define MELEMS (GTOT * HH)      // 4194304 elements

// Scratch (__device__ globals; no allocation allowed)
__device__ __half  g_mh[MELEMS];   // m[node,h] fp16 (8 MB)
__device__ float   g_acc[MELEMS];  // segment-sum accumulator (16 MB)
__device__ float4  g_grid4[GTOT];  // packed grid coords

// Packed weights (pack_kernel fills g_pack; one D2D memcpy -> c_pack)
struct Pack {
    float2 w1t[CIN * (HH / 2)];    // [c][hp] = {W1[2hp,c], W1[2hp+1,c]}
    float2 w2t[HH * (COUT / 2)];   // [h][op] = {W2[2op,h], W2[2op+1,h]}
    float  b1[HH];
    float  sc[HH];                 // sqrt((bw/pi)^3)
    float  nb[HH];                 // -bw * log2(e)
    float  b2[COUT];
};
__device__  Pack g_pack;
__constant__ Pack c_pack;

// ---- f32x2 helpers ----
__device__ __forceinline__ unsigned long long pk2(float lo, float hi) {
    unsigned long long r;
    asm("mov.b64 %0, {%1,%2};" : "=l"(r) : "f"(lo), "f"(hi));
    return r;
}
__device__ __forceinline__ float2 upk2(unsigned long long v) {
    float2 r;
    asm("mov.b64 {%0,%1}, %2;" : "=f"(r.x), "=f"(r.y) : "l"(v));
    return r;
}
__device__ __forceinline__ void ffma2(unsigned long long& acc,
                                      unsigned long long a,
                                      unsigned long long b) {
    asm("fma.rn.f32x2 %0, %1, %2, %0;" : "+l"(acc) : "l"(a), "l"(b));
}

// ---------------------------------------------------------------------------
// Prep: pack W1/W2 pairs + fold bw transforms. One block.
// ---------------------------------------------------------------------------
__global__ void pack_kernel(const float* __restrict__ W1,
                            const float* __restrict__ b1,
                            const float* __restrict__ W2,
                            const float* __restrict__ b2,
                            const float* __restrict__ bw) {
    int t = threadIdx.x;
    for (int i = t; i < CIN * (HH / 2); i += blockDim.x) {
        int c  = i / (HH / 2);
        int hp = i % (HH / 2);
        g_pack.w1t[i] = make_float2(W1[(2 * hp) * CIN + c],
                                    W1[(2 * hp + 1) * CIN + c]);
    }
    for (int i = t; i < HH * (COUT / 2); i += blockDim.x) {
        int h  = i / (COUT / 2);
        int op = i % (COUT / 2);
        g_pack.w2t[i] = make_float2(W2[(2 * op) * HH + h],
                                    W2[(2 * op + 1) * HH + h]);
    }
    if (t < HH) {
        g_pack.b1[t] = b1[t];
        float w = bw[t];
        float r = w * 0.3183098861837907f;          // bw/pi
        g_pack.sc[t] = sqrtf(r * r * r);
        g_pack.nb[t] = -w * 1.4426950408889634f;    // -bw*log2e
        g_pack.b2[t] = b2[t];
    }
}

// ---------------------------------------------------------------------------
// gemm1 fused (1 node/thread, f32x2):
//   m_h[g,h] = half((W1x+b1)*gw*sc[h]) ; acc[g,:]=0 ; grid4 pack.
// ---------------------------------------------------------------------------
__global__ void gemm1_kernel(const float* __restrict__ x,
                             const float* __restrict__ gw,
                             const float* __restrict__ grid) {
    int g = blockIdx.x * blockDim.x + threadIdx.x;   // node id
    int b = g >> 15;                                 // NN = 2^15
    int n = g & (NN - 1);
    const float* xb = x + (size_t)b * CIN * NN + n;

    const unsigned long long* w1u =
        reinterpret_cast<const unsigned long long*>(c_pack.w1t);

    unsigned long long acc2[HH / 2];
#pragma unroll
    for (int hp = 0; hp < HH / 2; hp++) acc2[hp] = 0ull;

#pragma unroll
    for (int c = 0; c < CIN; c++) {
        float xv = xb[(size_t)c * NN];               // coalesced
        unsigned long long xx = pk2(xv, xv);
#pragma unroll
        for (int hp = 0; hp < HH / 2; hp++)
            ffma2(acc2[hp], w1u[c * (HH / 2) + hp], xx);
    }

    float w = gw[g];
    uint4 ov[4];                                     // 32 halves = 64 B
    unsigned int* oh = reinterpret_cast<unsigned int*>(ov);
#pragma unroll
    for (int hp = 0; hp < HH / 2; hp++) {
        float2 a = upk2(acc2[hp]);
        float m0 = (a.x + c_pack.b1[2 * hp])     * w * c_pack.sc[2 * hp];
        float m1 = (a.y + c_pack.b1[2 * hp + 1]) * w * c_pack.sc[2 * hp + 1];
        __half2 h2 = __floats2half2_rn(m0, m1);
        oh[hp] = *reinterpret_cast<unsigned int*>(&h2);
    }
    uint4* mo = reinterpret_cast<uint4*>(g_mh + (size_t)g * HH);
#pragma unroll
    for (int q = 0; q < 4; q++) mo[q] = ov[q];

    float4* ao = reinterpret_cast<float4*>(g_acc + (size_t)g * HH);
#pragma unroll
    for (int j = 0; j < HH / 4; j++) ao[j] = make_float4(0.f, 0.f, 0.f, 0.f);

    const float* gp = grid + (size_t)g * PP;
    g_grid4[g] = make_float4(gp[0], gp[1], gp[2], 0.f);
}

// ---------------------------------------------------------------------------
// Edge kernel: byte-identical structure to round 6 (65us, known floor).
// Warp owns 32 edges; phase 2 retires 4 edges/iter via red.global.add.v4.f32.
// ---------------------------------------------------------------------------
__global__ void edge_kernel(const int* __restrict__ es,
                            const int* __restrict__ ed) {
    __shared__ float4 stage[8][32];                  // 8 warps/block
    int tid  = blockIdx.x * blockDim.x + threadIdx.x;
    int lane = threadIdx.x & 31;
    int w    = threadIdx.x >> 5;

    // ---- phase 1: lane = edge ----
    int e   = tid;
    int b   = e >> 19;                               // NN*KK = 2^19
    int off = b << 15;                               // b * NN
    int s   = __ldg(es + e) + off;
    int d   = __ldg(ed + e) + off;

    float4 gs = g_grid4[s];
    float4 gd = g_grid4[d];
    float dx = gs.x - gd.x;
    float dy = gs.y - gd.y;
    float dz = gs.z - gd.z;
    float d2 = dx * dx + dy * dy + dz * dz;

    stage[w][lane] = make_float4(__int_as_float(s * HH),
                                 __int_as_float(d * HH), d2, 0.f);
    __syncwarp();

    // ---- phase 2: grp = edge of quad, c0 = first of 4 channels ----
    int grp = lane >> 3;                             // 0..3
    int c0  = (lane & 7) * 4;                        // 0,4,...,28

    float nb0 = c_pack.nb[c0];
    float nb1 = c_pack.nb[c0 + 1];
    float nb2 = c_pack.nb[c0 + 2];
    float nb3 = c_pack.nb[c0 + 3];

#pragma unroll
    for (int i = 0; i < 32; i += 4) {
        float4 p  = stage[w][i + grp];               // 4-way LDS.128 broadcast
        int   si  = __float_as_int(p.x);
        int   di  = __float_as_int(p.y);
        float d2i = p.z;

        unsigned long long mraw =
            *reinterpret_cast<const unsigned long long*>(g_mh + si + c0);
        __half2 hA = *reinterpret_cast<__half2*>(&mraw);
        __half2 hB = *(reinterpret_cast<__half2*>(&mraw) + 1);
        float2 fA = __half22float2(hA);
        float2 fB = __half22float2(hB);

        float e0, e1, e2, e3;
        asm("ex2.approx.f32 %0, %1;" : "=f"(e0) : "f"(nb0 * d2i));
        asm("ex2.approx.f32 %0, %1;" : "=f"(e1) : "f"(nb1 * d2i));
        asm("ex2.approx.f32 %0, %1;" : "=f"(e2) : "f"(nb2 * d2i));
        asm("ex2.approx.f32 %0, %1;" : "=f"(e3) : "f"(nb3 * d2i));

        float v0 = fA.x * e0;
        float v1 = fA.y * e1;
        float v2 = fB.x * e2;
        float v3 = fB.y * e3;

        asm volatile("red.global.add.v4.f32 [%0], {%1, %2, %3, %4};"
                     :: "l"(g_acc + di + c0),
                        "f"(v0), "f"(v1), "f"(v2), "f"(v3)
                     : "memory");
    }
}

// ---------------------------------------------------------------------------
// gemm2 (f32x2 over output pairs): out[b,o,n] = sum_h W2[o,h]*acc[g,h] + b2[o]
// ---------------------------------------------------------------------------
__global__ void gemm2_kernel(float* __restrict__ out) {
    int g = blockIdx.x * blockDim.x + threadIdx.x;
    int b = g >> 15;
    int n = g & (NN - 1);

    float a[HH];
    const float4* av = reinterpret_cast<const float4*>(g_acc + (size_t)g * HH);
#pragma unroll
    for (int i = 0; i < HH / 4; i++) {
        float4 v = av[i];
        a[4 * i + 0] = v.x;
        a[4 * i + 1] = v.y;
        a[4 * i + 2] = v.z;
        a[4 * i + 3] = v.w;
    }

    const unsigned long long* w2u =
        reinterpret_cast<const unsigned long long*>(c_pack.w2t);

    unsigned long long s2[COUT / 2];
#pragma unroll
    for (int op = 0; op < COUT / 2; op++)
        s2[op] = pk2(c_pack.b2[2 * op], c_pack.b2[2 * op + 1]);

#pragma unroll
    for (int h = 0; h < HH; h++) {
        unsigned long long aa = pk2(a[h], a[h]);
#pragma unroll
        for (int op = 0; op < COUT / 2; op++)
            ffma2(s2[op], w2u[h * (COUT / 2) + op], aa);
    }

    float* ob = out + (size_t)b * COUT * NN + n;
#pragma unroll
    for (int op = 0; op < COUT / 2; op++) {
        float2 v = upk2(s2[op]);
        ob[(size_t)(2 * op) * NN]     = v.x;
        ob[(size_t)(2 * op + 1) * NN] = v.y;
    }
}

// ---------------------------------------------------------------------------
// Launcher
// inputs: 0:x 1:grid 2:grid_weight 3:edge_src 4:edge_dst 5:W1 6:b1 7:W2 8:b2 9:baseweight
// ---------------------------------------------------------------------------
extern "C" void kernel_launch(void* const* d_in, const int* in_sizes, int n_in,
                              void* d_out, int out_size) {
    const float* x    = (const float*)d_in[0];
    const float* grid = (const float*)d_in[1];
    const float* gw   = (const float*)d_in[2];
    const int*   es   = (const int*)d_in[3];
    const int*   ed   = (const int*)d_in[4];
    const float* W1   = (const float*)d_in[5];
    const float* b1   = (const float*)d_in[6];
    const float* W2   = (const float*)d_in[7];
    const float* b2   = (const float*)d_in[8];
    const float* bw   = (const float*)d_in[9];
    float* out = (float*)d_out;

    // 0) pack weights on device, stage into constant bank (single D2D copy)
    pack_kernel<<<1, 256>>>(W1, b1, W2, b2, bw);
    void* packAddr = nullptr;
    cudaGetSymbolAddress(&packAddr, g_pack);
    cudaMemcpyToSymbolAsync(c_pack, packAddr, sizeof(Pack), 0,
                            cudaMemcpyDeviceToDevice, 0);

    // 1) fused fc1 (f32x2) + gauss-norm + grid_weight ; zero acc ; pack grid
    gemm1_kernel<<<GTOT / 256, 256>>>(x, gw, grid);

    // 2) edge scatter: 32 edges per warp, two-phase, RED.v4
    edge_kernel<<<ETOT / 256, 256>>>(es, ed);

    // 3) fc2 (f32x2) + transpose to (B, COUT, N)
    gemm2_kernel<<<GTOT / 256, 256>>>(out);
}

// round 10
// speedup vs baseline: 2.2246x; 1.2281x over previous
#include <cuda_runtime.h>
#include <cuda_bf16.h>
#include <cuda_fp16.h>
#include <math.h>

// Fixed problem shape
#define BB   4
#define NN   32768
#define KK   16
#define CIN  32
#define HH   32
#define COUT 32
#define PP   3

#define GTOT (BB * NN)          // 131072 nodes
#define ETOT (BB * NN * KK)     // 2097152 edges
#define MELEMS (GTOT * HH)      // 4194304 elements

// Scratch (__device__ globals; no allocation allowed)
__device__ __half  g_mh[MELEMS];    // m[node,h] fp16 (8 MB)
__device__ __half  g_acch[MELEMS];  // segment-sum accumulator fp16 (8 MB)
__device__ float4  g_grid4[GTOT];   // packed grid coords

// Packed weights (pack_kernel fills g_pack; one D2D memcpy -> c_pack)
struct Pack {
    float2 w1t[CIN * (HH / 2)];    // [c][hp] = {W1[2hp,c], W1[2hp+1,c]}
    float2 w2t[HH * (COUT / 2)];   // [h][op] = {W2[2op,h], W2[2op+1,h]}
    float  b1[HH];
    float  sc[HH];                 // sqrt((bw/pi)^3)
    float  nb[HH];                 // -bw * log2(e)
    float  b2[COUT];
};
__device__  Pack g_pack;
__constant__ Pack c_pack;

// ---- f32x2 helpers ----
__device__ __forceinline__ unsigned long long pk2(float lo, float hi) {
    unsigned long long r;
    asm("mov.b64 %0, {%1,%2};" : "=l"(r) : "f"(lo), "f"(hi));
    return r;
}
__device__ __forceinline__ float2 upk2(unsigned long long v) {
    float2 r;
    asm("mov.b64 {%0,%1}, %2;" : "=f"(r.x), "=f"(r.y) : "l"(v));
    return r;
}
__device__ __forceinline__ void ffma2(unsigned long long& acc,
                                      unsigned long long a,
                                      unsigned long long b) {
    asm("fma.rn.f32x2 %0, %1, %2, %0;" : "+l"(acc) : "l"(a), "l"(b));
}

// ---------------------------------------------------------------------------
// Prep: pack W1/W2 pairs + fold bw transforms. One block.
// ---------------------------------------------------------------------------
__global__ void pack_kernel(const float* __restrict__ W1,
                            const float* __restrict__ b1,
                            const float* __restrict__ W2,
                            const float* __restrict__ b2,
                            const float* __restrict__ bw) {
    int t = threadIdx.x;
    for (int i = t; i < CIN * (HH / 2); i += blockDim.x) {
        int c  = i / (HH / 2);
        int hp = i % (HH / 2);
        g_pack.w1t[i] = make_float2(W1[(2 * hp) * CIN + c],
                                    W1[(2 * hp + 1) * CIN + c]);
    }
    for (int i = t; i < HH * (COUT / 2); i += blockDim.x) {
        int h  = i / (COUT / 2);
        int op = i % (COUT / 2);
        g_pack.w2t[i] = make_float2(W2[(2 * op) * HH + h],
                                    W2[(2 * op + 1) * HH + h]);
    }
    if (t < HH) {
        g_pack.b1[t] = b1[t];
        float w = bw[t];
        float r = w * 0.3183098861837907f;          // bw/pi
        g_pack.sc[t] = sqrtf(r * r * r);
        g_pack.nb[t] = -w * 1.4426950408889634f;    // -bw*log2e
        g_pack.b2[t] = b2[t];
    }
}

// ---------------------------------------------------------------------------
// gemm1 fused (1 node/thread, f32x2):
//   m_h[g,h] = half((W1x+b1)*gw*sc[h]) ; acch[g,:]=0 ; grid4 pack.
// ---------------------------------------------------------------------------
__global__ void gemm1_kernel(const float* __restrict__ x,
                             const float* __restrict__ gw,
                             const float* __restrict__ grid) {
    int g = blockIdx.x * blockDim.x + threadIdx.x;   // node id
    int b = g >> 15;                                 // NN = 2^15
    int n = g & (NN - 1);
    const float* xb = x + (size_t)b * CIN * NN + n;

    const unsigned long long* w1u =
        reinterpret_cast<const unsigned long long*>(c_pack.w1t);

    unsigned long long acc2[HH / 2];
#pragma unroll
    for (int hp = 0; hp < HH / 2; hp++) acc2[hp] = 0ull;

#pragma unroll
    for (int c = 0; c < CIN; c++) {
        float xv = xb[(size_t)c * NN];               // coalesced
        unsigned long long xx = pk2(xv, xv);
#pragma unroll
        for (int hp = 0; hp < HH / 2; hp++)
            ffma2(acc2[hp], w1u[c * (HH / 2) + hp], xx);
    }

    float w = gw[g];
    uint4 ov[4];                                     // 32 halves = 64 B
    unsigned int* oh = reinterpret_cast<unsigned int*>(ov);
#pragma unroll
    for (int hp = 0; hp < HH / 2; hp++) {
        float2 a = upk2(acc2[hp]);
        float m0 = (a.x + c_pack.b1[2 * hp])     * w * c_pack.sc[2 * hp];
        float m1 = (a.y + c_pack.b1[2 * hp + 1]) * w * c_pack.sc[2 * hp + 1];
        __half2 h2 = __floats2half2_rn(m0, m1);
        oh[hp] = *reinterpret_cast<unsigned int*>(&h2);
    }
    uint4* mo = reinterpret_cast<uint4*>(g_mh + (size_t)g * HH);
#pragma unroll
    for (int q = 0; q < 4; q++) mo[q] = ov[q];

    // zero fp16 accumulator row (64 B)
    uint4* ao = reinterpret_cast<uint4*>(g_acch + (size_t)g * HH);
#pragma unroll
    for (int q = 0; q < 4; q++) ao[q] = make_uint4(0, 0, 0, 0);

    const float* gp = grid + (size_t)g * PP;
    g_grid4[g] = make_float4(gp[0], gp[1], gp[2], 0.f);
}

// ---------------------------------------------------------------------------
// Edge kernel: warp owns 32 edges.
// Phase 1 (lane = edge): coalesced index loads, float4 grid gathers, d2 -> smem.
// Phase 2 (4 lanes per edge, 8 channels per lane): 8 edges retired per iter;
//   ONE red.global.add.noftz.v4.f16x2 (16B/lane -> 64B row) per iteration.
// ---------------------------------------------------------------------------
__global__ void edge_kernel(const int* __restrict__ es,
                            const int* __restrict__ ed) {
    __shared__ float4 stage[8][32];                  // 8 warps/block
    int tid  = blockIdx.x * blockDim.x + threadIdx.x;
    int lane = threadIdx.x & 31;
    int w    = threadIdx.x >> 5;

    // ---- phase 1: lane = edge ----
    int e   = tid;
    int b   = e >> 19;                               // NN*KK = 2^19
    int off = b << 15;                               // b * NN
    int s   = __ldg(es + e) + off;
    int d   = __ldg(ed + e) + off;

    float4 gs = g_grid4[s];
    float4 gd = g_grid4[d];
    float dx = gs.x - gd.x;
    float dy = gs.y - gd.y;
    float dz = gs.z - gd.z;
    float d2 = dx * dx + dy * dy + dz * dz;

    stage[w][lane] = make_float4(__int_as_float(s * HH),
                                 __int_as_float(d * HH), d2, 0.f);
    __syncwarp();

    // ---- phase 2: grp = edge of oct, c0 = first of 8 channels ----
    int grp = lane >> 2;                             // 0..7
    int c0  = (lane & 3) * 8;                        // 0,8,16,24

    float nb[8];
#pragma unroll
    for (int j = 0; j < 8; j++) nb[j] = c_pack.nb[c0 + j];

#pragma unroll
    for (int i = 0; i < 32; i += 8) {
        float4 p  = stage[w][i + grp];               // 8-way LDS.128 broadcast
        int   si  = __float_as_int(p.x);
        int   di  = __float_as_int(p.y);
        float d2i = p.z;

        // 8 fp16 m values: one 16B load (row is 64B, 4 lanes cover it)
        uint4 mraw = *reinterpret_cast<const uint4*>(g_mh + si + c0);
        const __half2* mh2 = reinterpret_cast<const __half2*>(&mraw);

        unsigned int vpk[4];
#pragma unroll
        for (int j = 0; j < 4; j++) {
            float2 mf = __half22float2(mh2[j]);
            float e0, e1;
            asm("ex2.approx.f32 %0, %1;" : "=f"(e0) : "f"(nb[2 * j] * d2i));
            asm("ex2.approx.f32 %0, %1;" : "=f"(e1) : "f"(nb[2 * j + 1] * d2i));
            __half2 h2 = __floats2half2_rn(mf.x * e0, mf.y * e1);
            vpk[j] = *reinterpret_cast<unsigned int*>(&h2);
        }

        // one vector fp16x2 reduction: 16B per lane, 16B-aligned
        asm volatile("red.global.add.noftz.v4.f16x2 [%0], {%1, %2, %3, %4};"
                     :: "l"(g_acch + di + c0),
                        "r"(vpk[0]), "r"(vpk[1]), "r"(vpk[2]), "r"(vpk[3])
                     : "memory");
    }
}

// ---------------------------------------------------------------------------
// gemm2 (f32x2 over output pairs): out[b,o,n] = sum_h W2[o,h]*acch[g,h] + b2[o]
// ---------------------------------------------------------------------------
__global__ void gemm2_kernel(float* __restrict__ out) {
    int g = blockIdx.x * blockDim.x + threadIdx.x;
    int b = g >> 15;
    int n = g & (NN - 1);

    float a[HH];
    const uint4* av = reinterpret_cast<const uint4*>(g_acch + (size_t)g * HH);
#pragma unroll
    for (int q = 0; q < 4; q++) {
        uint4 r = av[q];
        const __half2* h2 = reinterpret_cast<const __half2*>(&r);
#pragma unroll
        for (int j = 0; j < 4; j++) {
            float2 f = __half22float2(h2[j]);
            a[q * 8 + 2 * j]     = f.x;
            a[q * 8 + 2 * j + 1] = f.y;
        }
    }

    const unsigned long long* w2u =
        reinterpret_cast<const unsigned long long*>(c_pack.w2t);

    unsigned long long s2[COUT / 2];
#pragma unroll
    for (int op = 0; op < COUT / 2; op++)
        s2[op] = pk2(c_pack.b2[2 * op], c_pack.b2[2 * op + 1]);

#pragma unroll
    for (int h = 0; h < HH; h++) {
        unsigned long long aa = pk2(a[h], a[h]);
#pragma unroll
        for (int op = 0; op < COUT / 2; op++)
            ffma2(s2[op], w2u[h * (COUT / 2) + op], aa);
    }

    float* ob = out + (size_t)b * COUT * NN + n;
#pragma unroll
    for (int op = 0; op < COUT / 2; op++) {
        float2 v = upk2(s2[op]);
        ob[(size_t)(2 * op) * NN]     = v.x;
        ob[(size_t)(2 * op + 1) * NN] = v.y;
    }
}

// ---------------------------------------------------------------------------
// Launcher
// inputs: 0:x 1:grid 2:grid_weight 3:edge_src 4:edge_dst 5:W1 6:b1 7:W2 8:b2 9:baseweight
// ---------------------------------------------------------------------------
extern "C" void kernel_launch(void* const* d_in, const int* in_sizes, int n_in,
                              void* d_out, int out_size) {
    const float* x    = (const float*)d_in[0];
    const float* grid = (const float*)d_in[1];
    const float* gw   = (const float*)d_in[2];
    const int*   es   = (const int*)d_in[3];
    const int*   ed   = (const int*)d_in[4];
    const float* W1   = (const float*)d_in[5];
    const float* b1   = (const float*)d_in[6];
    const float* W2   = (const float*)d_in[7];
    const float* b2   = (const float*)d_in[8];
    const float* bw   = (const float*)d_in[9];
    float* out = (float*)d_out;

    // 0) pack weights on device, stage into constant bank (single D2D copy)
    pack_kernel<<<1, 256>>>(W1, b1, W2, b2, bw);
    void* packAddr = nullptr;
    cudaGetSymbolAddress(&packAddr, g_pack);
    cudaMemcpyToSymbolAsync(c_pack, packAddr, sizeof(Pack), 0,
                            cudaMemcpyDeviceToDevice, 0);

    // 1) fused fc1 (f32x2) + gauss-norm + grid_weight ; zero acc ; pack grid
    gemm1_kernel<<<GTOT / 256, 256>>>(x, gw, grid);

    // 2) edge scatter: 32 edges per warp, two-phase, RED.v4.f16x2
    edge_kernel<<<ETOT / 256, 256>>>(es, ed);

    // 3) fc2 (f32x2) + transpose to (B, COUT, N)
    gemm2_kernel<<<GTOT / 256, 256>>>(out);
}